// round 2
// baseline (speedup 1.0000x reference)
#include <cuda_runtime.h>
#include <cstdint>

// Transformer_66529043415377: flow-driven bilinear warp with the reference's
// quirky clamps (y in [0, C-1]=[0,2], x in [0, H-1]=[0,511]) and raw
// [N,3] channel-interleaved output layout.
//
// CRITICAL: the final 4-term weighted sum must use the reference's exact
// rounding order (round each product, left-assoc adds, NO fma contraction).
// When y0==y1 (the common clamped case) wb==-wa and B==A exactly, and the
// reference order cancels to an exact 0.0; an FFMA chain leaves ~250*eps
// garbage that dominates the (mostly-zero) reference norm.

namespace {
constexpr int B  = 16;
constexpr int H  = 512;
constexpr int W  = 512;
constexpr int HW = H * W;           // 262144
constexpr int N  = B * HW;          // 4194304 pixels
constexpr int PIX_PER_THREAD = 4;
constexpr int THREADS = 256;
}

__global__ __launch_bounds__(THREADS)
void transformer_warp_kernel(const float* __restrict__ flow,
                             const float* __restrict__ pqf,
                             float* __restrict__ out)
{
    const int t = blockIdx.x * blockDim.x + threadIdx.x;
    const int i = t * PIX_PER_THREAD;           // base pixel index
    if (i >= N) return;

    const int b   = i >> 18;                    // / HW
    const int rem = i & (HW - 1);
    const int h   = rem >> 9;                   // / W
    const int w   = rem & (W - 1);

    // flow[b,0,:,:] and flow[b,1,:,:]; rem is a multiple of 4 -> 16B aligned
    const float* fbase = flow + (size_t)b * 2 * HW + rem;
    const float4 dx4 = *reinterpret_cast<const float4*>(fbase);
    const float4 dy4 = *reinterpret_cast<const float4*>(fbase + HW);

    const float dxs[4] = {dx4.x, dx4.y, dx4.z, dx4.w};
    const float dys[4] = {dy4.x, dy4.y, dy4.z, dy4.w};

    float res[12];

    const float yf    = (float)h;
    const int   baseb = b << 9;                 // b * dim1 (=W=512)

#pragma unroll
    for (int j = 0; j < 4; ++j) {
        // dx*64 is exact (power-of-two), so one rounding either way -> matches ref
        const float x = __fadd_rn((float)(w + j), __fmul_rn(dxs[j], 64.0f));
        const float y = __fadd_rn(yf,             __fmul_rn(dys[j], 64.0f));

        float x0f = floorf(x);
        float y0f = floorf(y);
        float x1f = __fadd_rn(x0f, 1.0f);
        float y1f = __fadd_rn(y0f, 1.0f);

        // faithful clamps: max_x = H-1 = 511, max_y = C-1 = 2
        x0f = fminf(fmaxf(x0f, 0.0f), 511.0f);
        x1f = fminf(fmaxf(x1f, 0.0f), 511.0f);
        y0f = fminf(fmaxf(y0f, 0.0f), 2.0f);
        y1f = fminf(fmaxf(y1f, 0.0f), 2.0f);

        const int ix0 = (int)x0f;
        const int ix1 = (int)x1f;
        const int iy0 = (int)y0f;
        const int iy1 = (int)y1f;

        const int idx_a = baseb + iy0 * HW + ix0;
        const int idx_b = baseb + iy1 * HW + ix0;
        const int idx_c = baseb + iy0 * HW + ix1;
        const int idx_d = baseb + iy1 * HW + ix1;

        // single-rounded weight products (sub, sub, mul — no fma pattern)
        const float wxa = __fsub_rn(x1f, x);
        const float wxc = __fsub_rn(x, x0f);
        const float wya = __fsub_rn(y1f, y);
        const float wyb = __fsub_rn(y, y0f);
        const float wa = __fmul_rn(wxa, wya);
        const float wb = __fmul_rn(wxa, wyb);
        const float wc = __fmul_rn(wxc, wya);
        const float wd = __fmul_rn(wxc, wyb);

        const float* pa = pqf + (size_t)idx_a * 3;
        const float* pb = pqf + (size_t)idx_b * 3;
        const float* pc = pqf + (size_t)idx_c * 3;
        const float* pd = pqf + (size_t)idx_d * 3;

#pragma unroll
        for (int c = 0; c < 3; ++c) {
            // exact reference order: ((wa*A + wb*B) + wc*C) + wd*D,
            // each product individually rounded, no contraction
            const float pA = __fmul_rn(wa, __ldg(pa + c));
            const float pB = __fmul_rn(wb, __ldg(pb + c));
            const float pC = __fmul_rn(wc, __ldg(pc + c));
            const float pD = __fmul_rn(wd, __ldg(pd + c));
            res[j * 3 + c] = __fadd_rn(__fadd_rn(__fadd_rn(pA, pB), pC), pD);
        }
    }

    // 12 consecutive floats at out + i*3; i % 4 == 0 -> 48B offset, 16B aligned
    float4* o = reinterpret_cast<float4*>(out + (size_t)i * 3);
    o[0] = make_float4(res[0], res[1], res[2],  res[3]);
    o[1] = make_float4(res[4], res[5], res[6],  res[7]);
    o[2] = make_float4(res[8], res[9], res[10], res[11]);
}

extern "C" void kernel_launch(void* const* d_in, const int* in_sizes, int n_in,
                              void* d_out, int out_size)
{
    const float* flow = (const float*)d_in[0];
    const float* pqf  = (const float*)d_in[1];
    float* out        = (float*)d_out;

    const int threads_total = N / PIX_PER_THREAD;      // 1,048,576
    const int blocks = threads_total / THREADS;        // 4096
    transformer_warp_kernel<<<blocks, THREADS>>>(flow, pqf, out);
}

// round 3
// speedup vs baseline: 2.3706x; 2.3706x over previous
#include <cuda_runtime.h>
#include <cstdint>

// Transformer_66529043415377: flow-driven bilinear warp with the reference's
// quirky clamps (y in [0, C-1]=[0,2], x in [0, H-1]=[0,511]) and raw
// [N,3] channel-interleaved output layout.
//
// Fast path: when clamped y0f == y1f (floor(y) not in {0,1}, ~99.7% of
// pixels), the reference's rounding order cancels EXACTLY to +0.0:
//   wb = -wa and wd = -wc exactly, idx_a==idx_b, idx_c==idx_d
//   => ((pA+pB)+pC)+pD = +0.0 in round-to-nearest.
// Those pixels need no gathers and no dx. We load dy first, test the 4
// pixels, and only touch dx/pqf on the rare active path.
//
// Active path keeps the reference's exact rounding order (round each
// product, left-assoc adds, NO fma contraction) for bit-exactness.

namespace {
constexpr int B  = 16;
constexpr int H  = 512;
constexpr int W  = 512;
constexpr int HW = H * W;           // 262144
constexpr int N  = B * HW;          // 4194304 pixels
constexpr int PIX_PER_THREAD = 4;
constexpr int THREADS = 256;
}

__global__ __launch_bounds__(THREADS)
void transformer_warp_kernel(const float* __restrict__ flow,
                             const float* __restrict__ pqf,
                             float* __restrict__ out)
{
    const int t = blockIdx.x * blockDim.x + threadIdx.x;
    const int i = t * PIX_PER_THREAD;           // base pixel index

    const int b   = i >> 18;                    // / HW
    const int rem = i & (HW - 1);
    const int h   = rem >> 9;                   // / W
    const int w   = rem & (W - 1);

    // flow[b,1,:,:] (dy plane); rem is a multiple of 4 -> 16B aligned
    const float* fbase = flow + (size_t)b * 2 * HW + rem;
    const float4 dy4 = *reinterpret_cast<const float4*>(fbase + HW);

    const float dys[4] = {dy4.x, dy4.y, dy4.z, dy4.w};
    const float yf = (float)h;

    float y0c[4], y1c[4], yv[4];
    bool  active[4];
    bool  any_active = false;

#pragma unroll
    for (int j = 0; j < 4; ++j) {
        // dy*64 is exact (power-of-two scale) -> rounding matches reference
        const float y = __fadd_rn(yf, __fmul_rn(dys[j], 64.0f));
        float y0f = floorf(y);
        float y1f = __fadd_rn(y0f, 1.0f);
        y0f = fminf(fmaxf(y0f, 0.0f), 2.0f);   // max_y = C-1 = 2 (faithful quirk)
        y1f = fminf(fmaxf(y1f, 0.0f), 2.0f);
        yv[j]  = y;
        y0c[j] = y0f;
        y1c[j] = y1f;
        active[j] = (y0f != y1f);               // distinct rows -> real work
        any_active |= active[j];
    }

    float4* o = reinterpret_cast<float4*>(out + (size_t)i * 3);

    if (!any_active) {
        // All four pixels cancel exactly to +0.0 in the reference order.
        const float4 z = make_float4(0.0f, 0.0f, 0.0f, 0.0f);
        o[0] = z; o[1] = z; o[2] = z;
        return;
    }

    // Rare path: at least one of the 4 pixels does a real bilinear gather.
    const float4 dx4 = *reinterpret_cast<const float4*>(fbase);
    const float dxs[4] = {dx4.x, dx4.y, dx4.z, dx4.w};

    const int baseb = b << 9;                   // b * dim1 (=W=512)
    float res[12];

#pragma unroll
    for (int j = 0; j < 4; ++j) {
        if (!active[j]) {
            res[j * 3 + 0] = 0.0f;
            res[j * 3 + 1] = 0.0f;
            res[j * 3 + 2] = 0.0f;
            continue;
        }

        const float x = __fadd_rn((float)(w + j), __fmul_rn(dxs[j], 64.0f));
        const float y = yv[j];

        float x0f = floorf(x);
        float x1f = __fadd_rn(x0f, 1.0f);
        x0f = fminf(fmaxf(x0f, 0.0f), 511.0f);  // max_x = H-1 = 511
        x1f = fminf(fmaxf(x1f, 0.0f), 511.0f);
        const float y0f = y0c[j];
        const float y1f = y1c[j];

        const int ix0 = (int)x0f;
        const int ix1 = (int)x1f;
        const int iy0 = (int)y0f;
        const int iy1 = (int)y1f;

        const int idx_a = baseb + iy0 * HW + ix0;
        const int idx_b = baseb + iy1 * HW + ix0;
        const int idx_c = baseb + iy0 * HW + ix1;
        const int idx_d = baseb + iy1 * HW + ix1;

        // single-rounded weight products (sub, sub, mul — no fma pattern)
        const float wxa = __fsub_rn(x1f, x);
        const float wxc = __fsub_rn(x, x0f);
        const float wya = __fsub_rn(y1f, y);
        const float wyb = __fsub_rn(y, y0f);
        const float wa = __fmul_rn(wxa, wya);
        const float wb = __fmul_rn(wxa, wyb);
        const float wc = __fmul_rn(wxc, wya);
        const float wd = __fmul_rn(wxc, wyb);

        const float* pa = pqf + (size_t)idx_a * 3;
        const float* pb = pqf + (size_t)idx_b * 3;
        const float* pc = pqf + (size_t)idx_c * 3;
        const float* pd = pqf + (size_t)idx_d * 3;

#pragma unroll
        for (int c = 0; c < 3; ++c) {
            // exact reference order: ((wa*A + wb*B) + wc*C) + wd*D,
            // each product individually rounded, no contraction
            const float pA = __fmul_rn(wa, __ldg(pa + c));
            const float pB = __fmul_rn(wb, __ldg(pb + c));
            const float pC = __fmul_rn(wc, __ldg(pc + c));
            const float pD = __fmul_rn(wd, __ldg(pd + c));
            res[j * 3 + c] = __fadd_rn(__fadd_rn(__fadd_rn(pA, pB), pC), pD);
        }
    }

    o[0] = make_float4(res[0], res[1], res[2],  res[3]);
    o[1] = make_float4(res[4], res[5], res[6],  res[7]);
    o[2] = make_float4(res[8], res[9], res[10], res[11]);
}

extern "C" void kernel_launch(void* const* d_in, const int* in_sizes, int n_in,
                              void* d_out, int out_size)
{
    const float* flow = (const float*)d_in[0];
    const float* pqf  = (const float*)d_in[1];
    float* out        = (float*)d_out;

    const int threads_total = N / PIX_PER_THREAD;      // 1,048,576
    const int blocks = threads_total / THREADS;        // 4096
    transformer_warp_kernel<<<blocks, THREADS>>>(flow, pqf, out);
}